// round 2
// baseline (speedup 1.0000x reference)
#include <cuda_runtime.h>
#include <math.h>

#define BI 256
#define BC 256
#define LR 36
#define TT 64
#define DD 1024
#define DR 256
#define EPS 1e-8f

// ---------------- scratch (device globals; no allocation allowed) ----------------
__device__ float g_pr[3 * DD];        // proj_w @ red_w  (3, D)
__device__ float g_pb2[3];            // proj_w @ red_b + proj_b
__device__ float g_cb2;               // ||conv_b||^2
__device__ float g_capv[BC * DD];     // l2-normalized caption means
__device__ float g_w[BC * 3];         // softmax filter weights
__device__ float g_bb[BC];            // conv_b . cap_v
__device__ float g_cmat[BI * 3 * DD]; // c[i,k,:]
__device__ float g_cc[BI * 3 * DD];   // conv_w @ c
__device__ float g_G[BI * 6];         // Gram cc_k . cc_k' (00,01,02,11,12,22)
__device__ float g_h[BI * 3];         // cc_k . conv_b
__device__ float g_dot[BI * 3 * BC];  // cc . cap_v^T

// ---------------- K0: tiny precompute ----------------
__global__ void k0_prep(const float* __restrict__ red_w, const float* __restrict__ red_b,
                        const float* __restrict__ proj_w, const float* __restrict__ proj_b,
                        const float* __restrict__ conv_b) {
    if (blockIdx.x < 8) {
        int d = blockIdx.x * 128 + threadIdx.x;
        float a0 = 0.f, a1 = 0.f, a2 = 0.f;
        for (int e = 0; e < DR; e++) {
            float rw = red_w[e * DD + d];
            a0 += proj_w[e] * rw;
            a1 += proj_w[DR + e] * rw;
            a2 += proj_w[2 * DR + e] * rw;
        }
        g_pr[d] = a0; g_pr[DD + d] = a1; g_pr[2 * DD + d] = a2;
    } else {
        __shared__ float s[128];
        int tid = threadIdx.x;
        for (int k = 0; k < 3; k++) {
            float p = 0.f;
            for (int e = tid; e < DR; e += 128) p += proj_w[k * DR + e] * red_b[e];
            s[tid] = p; __syncthreads();
            for (int off = 64; off > 0; off >>= 1) { if (tid < off) s[tid] += s[tid + off]; __syncthreads(); }
            if (tid == 0) g_pb2[k] = s[0] + proj_b[k];
            __syncthreads();
        }
        float c = 0.f;
        for (int d = tid; d < DD; d += 128) { float v = conv_b[d]; c += v * v; }
        s[tid] = c; __syncthreads();
        for (int off = 64; off > 0; off >>= 1) { if (tid < off) s[tid] += s[tid + off]; __syncthreads(); }
        if (tid == 0) g_cb2 = s[0];
    }
}

// ---------------- K1: caption pooling + softmax weights ----------------
__global__ void k1_caption(const float* __restrict__ cap, const int* __restrict__ lens,
                           const float* __restrict__ conv_b) {
    int b = blockIdx.x;
    int tid = threadIdx.x; // 256 threads, 4 channels each
    int len = lens[b];
    float acc[4] = {0.f, 0.f, 0.f, 0.f};
    const float* base = cap + (size_t)b * TT * DD;
    for (int t = 0; t < len; t++) {
        const float* row = base + t * DD;
        #pragma unroll
        for (int j = 0; j < 4; j++) acc[j] += row[tid + 256 * j];
    }
    float invlen = 1.0f / (float)len;
    #pragma unroll
    for (int j = 0; j < 4; j++) acc[j] *= invlen;

    __shared__ float s[256];
    __shared__ float res[6];
    float vals[5];
    vals[0] = acc[0] * acc[0] + acc[1] * acc[1] + acc[2] * acc[2] + acc[3] * acc[3];
    #pragma unroll
    for (int k = 0; k < 3; k++) {
        float v = 0.f;
        #pragma unroll
        for (int j = 0; j < 4; j++) v += g_pr[k * DD + tid + 256 * j] * acc[j];
        vals[1 + k] = v;
    }
    {
        float v = 0.f;
        #pragma unroll
        for (int j = 0; j < 4; j++) v += conv_b[tid + 256 * j] * acc[j];
        vals[4] = v;
    }
    for (int r = 0; r < 5; r++) {
        s[tid] = vals[r]; __syncthreads();
        for (int off = 128; off > 0; off >>= 1) { if (tid < off) s[tid] += s[tid + off]; __syncthreads(); }
        if (tid == 0) res[r] = s[0];
        __syncthreads();
    }
    if (tid == 0) {
        float inv = 1.0f / (sqrtf(res[0]) + EPS);
        float l0 = res[1] + g_pb2[0], l1 = res[2] + g_pb2[1], l2 = res[3] + g_pb2[2];
        float m = fmaxf(l0, fmaxf(l1, l2));
        float e0 = expf(l0 - m), e1 = expf(l1 - m), e2 = expf(l2 - m);
        float si = 1.0f / (e0 + e1 + e2);
        g_w[b * 3 + 0] = e0 * si;
        g_w[b * 3 + 1] = e1 * si;
        g_w[b * 3 + 2] = e2 * si;
        g_bb[b] = res[4] * inv;
        res[5] = inv;
    }
    __syncthreads();
    float inv = res[5];
    #pragma unroll
    for (int j = 0; j < 4; j++) g_capv[b * DD + tid + 256 * j] = acc[j] * inv;
}

// ---------------- K2: image shifted region sums ----------------
__global__ void k2_image(const float* __restrict__ img) {
    int i = blockIdx.x;
    int tid = threadIdx.x;
    const float* base = img + (size_t)i * LR * DD;
    float acc[4] = {0.f, 0.f, 0.f, 0.f}, r0[4], rL[4];
    #pragma unroll
    for (int j = 0; j < 4; j++) r0[j] = base[tid + 256 * j];
    for (int t = 0; t < LR; t++) {
        #pragma unroll
        for (int j = 0; j < 4; j++) acc[j] += base[t * DD + tid + 256 * j];
    }
    #pragma unroll
    for (int j = 0; j < 4; j++) rL[j] = base[(LR - 1) * DD + tid + 256 * j];
    const float invL = 1.0f / (float)LR;
    #pragma unroll
    for (int j = 0; j < 4; j++) {
        int d = tid + 256 * j;
        g_cmat[(size_t)(i * 3 + 0) * DD + d] = (acc[j] - rL[j]) * invL;
        g_cmat[(size_t)(i * 3 + 1) * DD + d] = acc[j] * invL;
        g_cmat[(size_t)(i * 3 + 2) * DD + d] = (acc[j] - r0[j]) * invL;
    }
}

// ---------------- GEMM NT: C[M,N] = A[M,K] * B[N,K]^T  (fp32 SIMT) ----------------
// BM=64, BN=64, BK=16, 128 threads, 8x4 microtile, register double-buffered gmem loads
template <int M, int N, int KA>
__device__ __forceinline__ void gemm_nt_body(const float* __restrict__ A,
                                             const float* __restrict__ B,
                                             float* __restrict__ C) {
    __shared__ float As[16][64];
    __shared__ float Bs[16][64];
    int t = threadIdx.x;
    int tx = t & 15;   // 16 col groups of 4
    int ty = t >> 4;   // 8 row groups of 8
    int bm = blockIdx.y * 64;
    int bn = blockIdx.x * 64;

    // per-thread gmem load coords (2 chunks of 128 threads cover 64 rows x 16 k)
    int r0 = t >> 2;            int kk0 = (t & 3) * 4;
    int r1 = (t + 128) >> 2;    int kk1 = ((t + 128) & 3) * 4;

    float acc[8][4];
    #pragma unroll
    for (int i = 0; i < 8; i++)
        #pragma unroll
        for (int j = 0; j < 4; j++) acc[i][j] = 0.f;

    // prefetch k-tile 0
    float4 va0 = *reinterpret_cast<const float4*>(&A[(size_t)(bm + r0) * KA + kk0]);
    float4 va1 = *reinterpret_cast<const float4*>(&A[(size_t)(bm + r1) * KA + kk1]);
    float4 vb0 = *reinterpret_cast<const float4*>(&B[(size_t)(bn + r0) * KA + kk0]);
    float4 vb1 = *reinterpret_cast<const float4*>(&B[(size_t)(bn + r1) * KA + kk1]);

    for (int k0 = 0; k0 < KA; k0 += 16) {
        // stage current tile to smem
        As[kk0 + 0][r0] = va0.x; As[kk0 + 1][r0] = va0.y; As[kk0 + 2][r0] = va0.z; As[kk0 + 3][r0] = va0.w;
        As[kk1 + 0][r1] = va1.x; As[kk1 + 1][r1] = va1.y; As[kk1 + 2][r1] = va1.z; As[kk1 + 3][r1] = va1.w;
        Bs[kk0 + 0][r0] = vb0.x; Bs[kk0 + 1][r0] = vb0.y; Bs[kk0 + 2][r0] = vb0.z; Bs[kk0 + 3][r0] = vb0.w;
        Bs[kk1 + 0][r1] = vb1.x; Bs[kk1 + 1][r1] = vb1.y; Bs[kk1 + 2][r1] = vb1.z; Bs[kk1 + 3][r1] = vb1.w;
        __syncthreads();

        // prefetch next tile while computing this one
        if (k0 + 16 < KA) {
            va0 = *reinterpret_cast<const float4*>(&A[(size_t)(bm + r0) * KA + k0 + 16 + kk0]);
            va1 = *reinterpret_cast<const float4*>(&A[(size_t)(bm + r1) * KA + k0 + 16 + kk1]);
            vb0 = *reinterpret_cast<const float4*>(&B[(size_t)(bn + r0) * KA + k0 + 16 + kk0]);
            vb1 = *reinterpret_cast<const float4*>(&B[(size_t)(bn + r1) * KA + k0 + 16 + kk1]);
        }

        #pragma unroll
        for (int kk = 0; kk < 16; kk++) {
            float a[8], bb[4];
            #pragma unroll
            for (int i = 0; i < 8; i++) a[i] = As[kk][ty * 8 + i];
            #pragma unroll
            for (int j = 0; j < 4; j++) bb[j] = Bs[kk][tx * 4 + j];
            #pragma unroll
            for (int i = 0; i < 8; i++)
                #pragma unroll
                for (int j = 0; j < 4; j++) acc[i][j] += a[i] * bb[j];
        }
        __syncthreads();
    }
    #pragma unroll
    for (int i = 0; i < 8; i++) {
        float4 v = make_float4(acc[i][0], acc[i][1], acc[i][2], acc[i][3]);
        *reinterpret_cast<float4*>(&C[(size_t)(bm + ty * 8 + i) * N + bn + tx * 4]) = v;
    }
}

__global__ void k3_gemm_cc(const float* __restrict__ conv_w) {
    gemm_nt_body<BI * 3, DD, DD>(g_cmat, conv_w, g_cc);
}
__global__ void k5_gemm_dot() {
    gemm_nt_body<BI * 3, BC, DD>(g_cc, g_capv, g_dot);
}

// ---------------- K4: per-image Gram + bias dots ----------------
__global__ void k4_gram(const float* __restrict__ conv_b) {
    int i = blockIdx.x;
    int tid = threadIdx.x; // 128
    const float* c0 = g_cc + (size_t)(i * 3 + 0) * DD;
    const float* c1 = c0 + DD;
    const float* c2 = c1 + DD;
    float a[9];
    #pragma unroll
    for (int r = 0; r < 9; r++) a[r] = 0.f;
    for (int d = tid; d < DD; d += 128) {
        float x0 = c0[d], x1 = c1[d], x2 = c2[d], cb = conv_b[d];
        a[0] += x0 * x0; a[1] += x0 * x1; a[2] += x0 * x2;
        a[3] += x1 * x1; a[4] += x1 * x2; a[5] += x2 * x2;
        a[6] += x0 * cb; a[7] += x1 * cb; a[8] += x2 * cb;
    }
    __shared__ float s[128];
    for (int r = 0; r < 9; r++) {
        s[tid] = a[r]; __syncthreads();
        for (int off = 64; off > 0; off >>= 1) { if (tid < off) s[tid] += s[tid + off]; __syncthreads(); }
        if (tid == 0) { if (r < 6) g_G[i * 6 + r] = s[0]; else g_h[i * 3 + (r - 6)] = s[0]; }
        __syncthreads();
    }
}

// ---------------- K6: final similarity ----------------
__global__ void k6_final(float* __restrict__ out) {
    int i = blockIdx.x;
    int b = threadIdx.x; // 256
    float w0 = g_w[b * 3 + 0], w1 = g_w[b * 3 + 1], w2 = g_w[b * 3 + 2];
    const float* dp = g_dot + (size_t)(i * 3) * BC + b;
    float num = w0 * dp[0] + w1 * dp[BC] + w2 * dp[2 * BC] + g_bb[b];
    const float* G = g_G + i * 6;
    const float* h = g_h + i * 3;
    float n2 = w0 * w0 * G[0] + 2.f * w0 * w1 * G[1] + 2.f * w0 * w2 * G[2]
             + w1 * w1 * G[3] + 2.f * w1 * w2 * G[4] + w2 * w2 * G[5]
             + 2.f * (w0 * h[0] + w1 * h[1] + w2 * h[2]) + g_cb2;
    out[i * BC + b] = num / (sqrtf(n2) + EPS);
}

// ---------------- launch ----------------
extern "C" void kernel_launch(void* const* d_in, const int* in_sizes, int n_in,
                              void* d_out, int out_size) {
    const float* img    = (const float*)d_in[0];
    const float* cap    = (const float*)d_in[1];
    const int*   lens   = (const int*)d_in[2];
    const float* red_w  = (const float*)d_in[3];
    const float* red_b  = (const float*)d_in[4];
    const float* proj_w = (const float*)d_in[5];
    const float* proj_b = (const float*)d_in[6];
    const float* conv_w = (const float*)d_in[7];
    const float* conv_b = (const float*)d_in[8];
    float* out = (float*)d_out;

    k0_prep<<<9, 128>>>(red_w, red_b, proj_w, proj_b, conv_b);
    k1_caption<<<BC, 256>>>(cap, lens, conv_b);
    k2_image<<<BI, 256>>>(img);
    k3_gemm_cc<<<dim3(DD / 64, (BI * 3) / 64), 128>>>(conv_w);
    k4_gram<<<BI, 128>>>(conv_b);
    k5_gemm_dot<<<dim3(BC / 64, (BI * 3) / 64), 128>>>();
    k6_final<<<BI, 256>>>(out);
}

// round 5
// speedup vs baseline: 1.3512x; 1.3512x over previous
#include <cuda_runtime.h>
#include <math.h>

#define BI 256
#define BC 256
#define LR 36
#define TT 64
#define DD 1024
#define DR 256
#define EPS 1e-8f

// ---------------- scratch (device globals; no allocation allowed) ----------------
__device__ float g_pr[3 * DD];        // proj_w @ red_w  (3, D)
__device__ float g_pb2[3];            // proj_w @ red_b + proj_b
__device__ float g_cb2;               // ||conv_b||^2
__device__ float g_capv[BC * DD];     // l2-normalized caption means
__device__ float g_w[BC * 3];         // softmax filter weights
__device__ float g_bb[BC];            // conv_b . cap_v
__device__ float g_cmat[BI * 3 * DD]; // c[i,k,:]
__device__ float g_cc[BI * 3 * DD];   // conv_w @ c
__device__ float g_G[BI * 6];         // Gram cc_k . cc_k'
__device__ float g_h[BI * 3];         // cc_k . conv_b
__device__ float g_dot[BI * 3 * BC];  // cc . cap_v^T

// ---------------- K0: tiny precompute (R2 verbatim) ----------------
__global__ void k0_prep(const float* __restrict__ red_w, const float* __restrict__ red_b,
                        const float* __restrict__ proj_w, const float* __restrict__ proj_b,
                        const float* __restrict__ conv_b) {
    if (blockIdx.x < 8) {
        int d = blockIdx.x * 128 + threadIdx.x;
        float a0 = 0.f, a1 = 0.f, a2 = 0.f;
        for (int e = 0; e < DR; e++) {
            float rw = red_w[e * DD + d];
            a0 += proj_w[e] * rw;
            a1 += proj_w[DR + e] * rw;
            a2 += proj_w[2 * DR + e] * rw;
        }
        g_pr[d] = a0; g_pr[DD + d] = a1; g_pr[2 * DD + d] = a2;
    } else {
        __shared__ float s[128];
        int tid = threadIdx.x;
        for (int k = 0; k < 3; k++) {
            float p = 0.f;
            for (int e = tid; e < DR; e += 128) p += proj_w[k * DR + e] * red_b[e];
            s[tid] = p; __syncthreads();
            for (int off = 64; off > 0; off >>= 1) { if (tid < off) s[tid] += s[tid + off]; __syncthreads(); }
            if (tid == 0) g_pb2[k] = s[0] + proj_b[k];
            __syncthreads();
        }
        float c = 0.f;
        for (int d = tid; d < DD; d += 128) { float v = conv_b[d]; c += v * v; }
        s[tid] = c; __syncthreads();
        for (int off = 64; off > 0; off >>= 1) { if (tid < off) s[tid] += s[tid + off]; __syncthreads(); }
        if (tid == 0) g_cb2 = s[0];
    }
}

// ---------------- K1: caption pooling + softmax weights (R2 verbatim) ----------------
__global__ void k1_caption(const float* __restrict__ cap, const int* __restrict__ lens,
                           const float* __restrict__ conv_b) {
    int b = blockIdx.x;
    int tid = threadIdx.x; // 256 threads, 4 channels each
    int len = lens[b];
    float acc[4] = {0.f, 0.f, 0.f, 0.f};
    const float* base = cap + (size_t)b * TT * DD;
    for (int t = 0; t < len; t++) {
        const float* row = base + t * DD;
        #pragma unroll
        for (int j = 0; j < 4; j++) acc[j] += row[tid + 256 * j];
    }
    float invlen = 1.0f / (float)len;
    #pragma unroll
    for (int j = 0; j < 4; j++) acc[j] *= invlen;

    __shared__ float s[256];
    __shared__ float res[6];
    float vals[5];
    vals[0] = acc[0] * acc[0] + acc[1] * acc[1] + acc[2] * acc[2] + acc[3] * acc[3];
    #pragma unroll
    for (int k = 0; k < 3; k++) {
        float v = 0.f;
        #pragma unroll
        for (int j = 0; j < 4; j++) v += g_pr[k * DD + tid + 256 * j] * acc[j];
        vals[1 + k] = v;
    }
    {
        float v = 0.f;
        #pragma unroll
        for (int j = 0; j < 4; j++) v += conv_b[tid + 256 * j] * acc[j];
        vals[4] = v;
    }
    for (int r = 0; r < 5; r++) {
        s[tid] = vals[r]; __syncthreads();
        for (int off = 128; off > 0; off >>= 1) { if (tid < off) s[tid] += s[tid + off]; __syncthreads(); }
        if (tid == 0) res[r] = s[0];
        __syncthreads();
    }
    if (tid == 0) {
        float inv = 1.0f / (sqrtf(res[0]) + EPS);
        float l0 = res[1] + g_pb2[0], l1 = res[2] + g_pb2[1], l2 = res[3] + g_pb2[2];
        float m = fmaxf(l0, fmaxf(l1, l2));
        float e0 = expf(l0 - m), e1 = expf(l1 - m), e2 = expf(l2 - m);
        float si = 1.0f / (e0 + e1 + e2);
        g_w[b * 3 + 0] = e0 * si;
        g_w[b * 3 + 1] = e1 * si;
        g_w[b * 3 + 2] = e2 * si;
        g_bb[b] = res[4] * inv;
        res[5] = inv;
    }
    __syncthreads();
    float inv = res[5];
    #pragma unroll
    for (int j = 0; j < 4; j++) g_capv[b * DD + tid + 256 * j] = acc[j] * inv;
}

// ---------------- K2: image shifted region sums (R2 verbatim) ----------------
__global__ void k2_image(const float* __restrict__ img) {
    int i = blockIdx.x;
    int tid = threadIdx.x;
    const float* base = img + (size_t)i * LR * DD;
    float acc[4] = {0.f, 0.f, 0.f, 0.f}, r0[4], rL[4];
    #pragma unroll
    for (int j = 0; j < 4; j++) r0[j] = base[tid + 256 * j];
    for (int t = 0; t < LR; t++) {
        #pragma unroll
        for (int j = 0; j < 4; j++) acc[j] += base[t * DD + tid + 256 * j];
    }
    #pragma unroll
    for (int j = 0; j < 4; j++) rL[j] = base[(LR - 1) * DD + tid + 256 * j];
    const float invL = 1.0f / (float)LR;
    #pragma unroll
    for (int j = 0; j < 4; j++) {
        int d = tid + 256 * j;
        g_cmat[(size_t)(i * 3 + 0) * DD + d] = (acc[j] - rL[j]) * invL;
        g_cmat[(size_t)(i * 3 + 1) * DD + d] = acc[j] * invL;
        g_cmat[(size_t)(i * 3 + 2) * DD + d] = (acc[j] - r0[j]) * invL;
    }
}

// ---------------- zero kernel (trivially spill-free) ----------------
__global__ void kzero(float* __restrict__ p, int n4) {
    int i = blockIdx.x * 256 + threadIdx.x;
    if (i < n4) reinterpret_cast<float4*>(p)[i] = make_float4(0.f, 0.f, 0.f, 0.f);
}

// ---------------- GEMM NT split-K: C[M,N] += A[:,kz] * B[:,kz]^T  (atomic epilogue) ----
// Body identical to R2's proven gemm (92 regs); only the pointer offsets by
// blockIdx.z and the epilogue uses atomicAdd.
template <int M, int N, int KA, int KLEN>
__device__ __forceinline__ void gemm_nt_atomic(const float* __restrict__ A,
                                               const float* __restrict__ B,
                                               float* __restrict__ C) {
    __shared__ float As[16][64];
    __shared__ float Bs[16][64];
    int t = threadIdx.x;
    int tx = t & 15;   // 16 col groups of 4
    int ty = t >> 4;   // 8 row groups of 8
    int bm = blockIdx.y * 64;
    int bn = blockIdx.x * 64;

    const float* Ab = A + blockIdx.z * KLEN;
    const float* Bb = B + blockIdx.z * KLEN;

    int r0 = t >> 2;            int kk0 = (t & 3) * 4;
    int r1 = (t + 128) >> 2;    int kk1 = ((t + 128) & 3) * 4;

    float acc[8][4];
    #pragma unroll
    for (int i = 0; i < 8; i++)
        #pragma unroll
        for (int j = 0; j < 4; j++) acc[i][j] = 0.f;

    // prefetch k-tile 0
    float4 va0 = *reinterpret_cast<const float4*>(&Ab[(size_t)(bm + r0) * KA + kk0]);
    float4 va1 = *reinterpret_cast<const float4*>(&Ab[(size_t)(bm + r1) * KA + kk1]);
    float4 vb0 = *reinterpret_cast<const float4*>(&Bb[(size_t)(bn + r0) * KA + kk0]);
    float4 vb1 = *reinterpret_cast<const float4*>(&Bb[(size_t)(bn + r1) * KA + kk1]);

    for (int k0 = 0; k0 < KLEN; k0 += 16) {
        As[kk0 + 0][r0] = va0.x; As[kk0 + 1][r0] = va0.y; As[kk0 + 2][r0] = va0.z; As[kk0 + 3][r0] = va0.w;
        As[kk1 + 0][r1] = va1.x; As[kk1 + 1][r1] = va1.y; As[kk1 + 2][r1] = va1.z; As[kk1 + 3][r1] = va1.w;
        Bs[kk0 + 0][r0] = vb0.x; Bs[kk0 + 1][r0] = vb0.y; Bs[kk0 + 2][r0] = vb0.z; Bs[kk0 + 3][r0] = vb0.w;
        Bs[kk1 + 0][r1] = vb1.x; Bs[kk1 + 1][r1] = vb1.y; Bs[kk1 + 2][r1] = vb1.z; Bs[kk1 + 3][r1] = vb1.w;
        __syncthreads();

        if (k0 + 16 < KLEN) {
            va0 = *reinterpret_cast<const float4*>(&Ab[(size_t)(bm + r0) * KA + k0 + 16 + kk0]);
            va1 = *reinterpret_cast<const float4*>(&Ab[(size_t)(bm + r1) * KA + k0 + 16 + kk1]);
            vb0 = *reinterpret_cast<const float4*>(&Bb[(size_t)(bn + r0) * KA + k0 + 16 + kk0]);
            vb1 = *reinterpret_cast<const float4*>(&Bb[(size_t)(bn + r1) * KA + k0 + 16 + kk1]);
        }

        #pragma unroll
        for (int kk = 0; kk < 16; kk++) {
            float a[8], bb[4];
            #pragma unroll
            for (int i = 0; i < 8; i++) a[i] = As[kk][ty * 8 + i];
            #pragma unroll
            for (int j = 0; j < 4; j++) bb[j] = Bs[kk][tx * 4 + j];
            #pragma unroll
            for (int i = 0; i < 8; i++)
                #pragma unroll
                for (int j = 0; j < 4; j++) acc[i][j] += a[i] * bb[j];
        }
        __syncthreads();
    }
    #pragma unroll
    for (int i = 0; i < 8; i++) {
        float* crow = &C[(size_t)(bm + ty * 8 + i) * N + bn + tx * 4];
        #pragma unroll
        for (int j = 0; j < 4; j++) atomicAdd(&crow[j], acc[i][j]);
    }
}

__global__ void k3_gemm_cc(const float* __restrict__ conv_w) {
    gemm_nt_atomic<BI * 3, DD, DD, 256>(g_cmat, conv_w, g_cc);
}
__global__ void k5_gemm_dot() {
    gemm_nt_atomic<BI * 3, BC, DD, 128>(g_cc, g_capv, g_dot);
}

// ---------------- K4: per-image Gram + bias dots (R2 verbatim) ----------------
__global__ void k4_gram(const float* __restrict__ conv_b) {
    int i = blockIdx.x;
    int tid = threadIdx.x; // 128
    const float* c0 = g_cc + (size_t)(i * 3 + 0) * DD;
    const float* c1 = c0 + DD;
    const float* c2 = c1 + DD;
    float a[9];
    #pragma unroll
    for (int r = 0; r < 9; r++) a[r] = 0.f;
    for (int d = tid; d < DD; d += 128) {
        float x0 = c0[d], x1 = c1[d], x2 = c2[d], cb = conv_b[d];
        a[0] += x0 * x0; a[1] += x0 * x1; a[2] += x0 * x2;
        a[3] += x1 * x1; a[4] += x1 * x2; a[5] += x2 * x2;
        a[6] += x0 * cb; a[7] += x1 * cb; a[8] += x2 * cb;
    }
    __shared__ float s[128];
    for (int r = 0; r < 9; r++) {
        s[tid] = a[r]; __syncthreads();
        for (int off = 64; off > 0; off >>= 1) { if (tid < off) s[tid] += s[tid + off]; __syncthreads(); }
        if (tid == 0) { if (r < 6) g_G[i * 6 + r] = s[0]; else g_h[i * 3 + (r - 6)] = s[0]; }
        __syncthreads();
    }
}

// ---------------- K6: final similarity (R2 verbatim) ----------------
__global__ void k6_final(float* __restrict__ out) {
    int i = blockIdx.x;
    int b = threadIdx.x; // 256
    float w0 = g_w[b * 3 + 0], w1 = g_w[b * 3 + 1], w2 = g_w[b * 3 + 2];
    const float* dp = g_dot + (size_t)(i * 3) * BC + b;
    float num = w0 * dp[0] + w1 * dp[BC] + w2 * dp[2 * BC] + g_bb[b];
    const float* G = g_G + i * 6;
    const float* h = g_h + i * 3;
    float n2 = w0 * w0 * G[0] + 2.f * w0 * w1 * G[1] + 2.f * w0 * w2 * G[2]
             + w1 * w1 * G[3] + 2.f * w1 * w2 * G[4] + w2 * w2 * G[5]
             + 2.f * (w0 * h[0] + w1 * h[1] + w2 * h[2]) + g_cb2;
    out[i * BC + b] = num / (sqrtf(n2) + EPS);
}

// ---------------- launch ----------------
extern "C" void kernel_launch(void* const* d_in, const int* in_sizes, int n_in,
                              void* d_out, int out_size) {
    const float* img    = (const float*)d_in[0];
    const float* cap    = (const float*)d_in[1];
    const int*   lens   = (const int*)d_in[2];
    const float* red_w  = (const float*)d_in[3];
    const float* red_b  = (const float*)d_in[4];
    const float* proj_w = (const float*)d_in[5];
    const float* proj_b = (const float*)d_in[6];
    const float* conv_w = (const float*)d_in[7];
    const float* conv_b = (const float*)d_in[8];
    float* out = (float*)d_out;

    float* cc_ptr = nullptr;
    float* dot_ptr = nullptr;
    cudaGetSymbolAddress((void**)&cc_ptr, g_cc);
    cudaGetSymbolAddress((void**)&dot_ptr, g_dot);

    k0_prep<<<9, 128>>>(red_w, red_b, proj_w, proj_b, conv_b);
    k1_caption<<<BC, 256>>>(cap, lens, conv_b);
    k2_image<<<BI, 256>>>(img);
    kzero<<<(BI * 3 * DD / 4 + 255) / 256, 256>>>(cc_ptr, BI * 3 * DD / 4);
    // k3: C(768x1024) += cmat * conv_w^T, split-K 4 -> 768 CTAs
    k3_gemm_cc<<<dim3(DD / 64, (BI * 3) / 64, 4), 128>>>(conv_w);
    k4_gram<<<BI, 128>>>(conv_b);
    kzero<<<(BI * 3 * BC / 4 + 255) / 256, 256>>>(dot_ptr, BI * 3 * BC / 4);
    // k5: dot(768x256) += cc * capv^T, split-K 8 -> 384 CTAs
    k5_gemm_dot<<<dim3(BC / 64, (BI * 3) / 64, 8), 128>>>();
    k6_final<<<BI, 256>>>(out);
}

// round 6
// speedup vs baseline: 1.4122x; 1.0451x over previous
#include <cuda_runtime.h>
#include <math.h>

#define BI 256
#define BC 256
#define LR 36
#define TT 64
#define DD 1024
#define DR 256
#define EPS 1e-8f

// ---------------- scratch (device globals; no allocation allowed) ----------------
__device__ float g_pr[3 * DD];        // proj_w @ red_w  (3, D)
__device__ float g_pb2[3];            // proj_w @ red_b + proj_b
__device__ float g_cb2;               // ||conv_b||^2
__device__ float g_capsum[BC * DD];   // raw caption sums (pre-normalization)
__device__ float g_capv[BC * DD];     // l2-normalized caption means
__device__ float g_w[BC * 3];         // softmax filter weights
__device__ float g_bb[BC];            // conv_b . cap_v
__device__ float g_cmat[BI * 3 * DD]; // c[i,k,:]
__device__ float g_cc[BI * 3 * DD];   // conv_w @ c
__device__ float g_G[BI * 6];         // Gram cc_k . cc_k'
__device__ float g_h[BI * 3];         // cc_k . conv_b
__device__ float g_dot[BI * 3 * BC];  // cc . cap_v^T

// ---------------- K0: tiny precompute ----------------
__global__ void k0_prep(const float* __restrict__ red_w, const float* __restrict__ red_b,
                        const float* __restrict__ proj_w, const float* __restrict__ proj_b,
                        const float* __restrict__ conv_b) {
    if (blockIdx.x < 8) {
        int d = blockIdx.x * 128 + threadIdx.x;
        float a0 = 0.f, a1 = 0.f, a2 = 0.f;
        for (int e = 0; e < DR; e++) {
            float rw = red_w[e * DD + d];
            a0 += proj_w[e] * rw;
            a1 += proj_w[DR + e] * rw;
            a2 += proj_w[2 * DR + e] * rw;
        }
        g_pr[d] = a0; g_pr[DD + d] = a1; g_pr[2 * DD + d] = a2;
    } else {
        __shared__ float s[128];
        int tid = threadIdx.x;
        for (int k = 0; k < 3; k++) {
            float p = 0.f;
            for (int e = tid; e < DR; e += 128) p += proj_w[k * DR + e] * red_b[e];
            s[tid] = p; __syncthreads();
            for (int off = 64; off > 0; off >>= 1) { if (tid < off) s[tid] += s[tid + off]; __syncthreads(); }
            if (tid == 0) g_pb2[k] = s[0] + proj_b[k];
            __syncthreads();
        }
        float c = 0.f;
        for (int d = tid; d < DD; d += 128) { float v = conv_b[d]; c += v * v; }
        s[tid] = c; __syncthreads();
        for (int off = 64; off > 0; off >>= 1) { if (tid < off) s[tid] += s[tid + off]; __syncthreads(); }
        if (tid == 0) g_cb2 = s[0];
    }
}

// ---------------- K1a: t-split caption sums (atomic accumulate) ----------------
// grid (BC, 4), block 256. Block (b, z) sums t in [z*16, min(len, z*16+16)).
__global__ void k1a_capsum(const float* __restrict__ cap, const int* __restrict__ lens) {
    int b = blockIdx.x;
    int z = blockIdx.y;
    int tid = threadIdx.x;
    int len = lens[b];
    int t0 = z * 16;
    if (t0 >= len) return;
    int t1 = min(len, t0 + 16);
    const float* base = cap + (size_t)b * TT * DD;
    float acc[4] = {0.f, 0.f, 0.f, 0.f};
    for (int t = t0; t < t1; t++) {
        const float* row = base + t * DD;
        #pragma unroll
        for (int j = 0; j < 4; j++) acc[j] += row[tid + 256 * j];
    }
    #pragma unroll
    for (int j = 0; j < 4; j++) atomicAdd(&g_capsum[b * DD + tid + 256 * j], acc[j]);
}

// ---------------- K1b: normalize + softmax weights (from pooled sums) ----------------
__global__ void k1b_caption(const int* __restrict__ lens, const float* __restrict__ conv_b) {
    int b = blockIdx.x;
    int tid = threadIdx.x; // 256 threads, 4 channels each
    int len = lens[b];
    float invlen = 1.0f / (float)len;
    float acc[4];
    #pragma unroll
    for (int j = 0; j < 4; j++) acc[j] = g_capsum[b * DD + tid + 256 * j] * invlen;

    __shared__ float s[256];
    __shared__ float res[6];
    float vals[5];
    vals[0] = acc[0] * acc[0] + acc[1] * acc[1] + acc[2] * acc[2] + acc[3] * acc[3];
    #pragma unroll
    for (int k = 0; k < 3; k++) {
        float v = 0.f;
        #pragma unroll
        for (int j = 0; j < 4; j++) v += g_pr[k * DD + tid + 256 * j] * acc[j];
        vals[1 + k] = v;
    }
    {
        float v = 0.f;
        #pragma unroll
        for (int j = 0; j < 4; j++) v += conv_b[tid + 256 * j] * acc[j];
        vals[4] = v;
    }
    for (int r = 0; r < 5; r++) {
        s[tid] = vals[r]; __syncthreads();
        for (int off = 128; off > 0; off >>= 1) { if (tid < off) s[tid] += s[tid + off]; __syncthreads(); }
        if (tid == 0) res[r] = s[0];
        __syncthreads();
    }
    if (tid == 0) {
        float inv = 1.0f / (sqrtf(res[0]) + EPS);
        float l0 = res[1] + g_pb2[0], l1 = res[2] + g_pb2[1], l2 = res[3] + g_pb2[2];
        float m = fmaxf(l0, fmaxf(l1, l2));
        float e0 = expf(l0 - m), e1 = expf(l1 - m), e2 = expf(l2 - m);
        float si = 1.0f / (e0 + e1 + e2);
        g_w[b * 3 + 0] = e0 * si;
        g_w[b * 3 + 1] = e1 * si;
        g_w[b * 3 + 2] = e2 * si;
        g_bb[b] = res[4] * inv;
        res[5] = inv;
    }
    __syncthreads();
    float inv = res[5];
    #pragma unroll
    for (int j = 0; j < 4; j++) g_capv[b * DD + tid + 256 * j] = acc[j] * inv;
}

// ---------------- K2: image shifted region sums ----------------
__global__ void k2_image(const float* __restrict__ img) {
    int i = blockIdx.x;
    int tid = threadIdx.x;
    const float* base = img + (size_t)i * LR * DD;
    float acc[4] = {0.f, 0.f, 0.f, 0.f}, r0[4], rL[4];
    #pragma unroll
    for (int j = 0; j < 4; j++) r0[j] = base[tid + 256 * j];
    for (int t = 0; t < LR; t++) {
        #pragma unroll
        for (int j = 0; j < 4; j++) acc[j] += base[t * DD + tid + 256 * j];
    }
    #pragma unroll
    for (int j = 0; j < 4; j++) rL[j] = base[(LR - 1) * DD + tid + 256 * j];
    const float invL = 1.0f / (float)LR;
    #pragma unroll
    for (int j = 0; j < 4; j++) {
        int d = tid + 256 * j;
        g_cmat[(size_t)(i * 3 + 0) * DD + d] = (acc[j] - rL[j]) * invL;
        g_cmat[(size_t)(i * 3 + 1) * DD + d] = acc[j] * invL;
        g_cmat[(size_t)(i * 3 + 2) * DD + d] = (acc[j] - r0[j]) * invL;
    }
}

// ---------------- zero kernel ----------------
__global__ void kzero(float* __restrict__ p, int n4) {
    int i = blockIdx.x * 256 + threadIdx.x;
    if (i < n4) reinterpret_cast<float4*>(p)[i] = make_float4(0.f, 0.f, 0.f, 0.f);
}

// ---------------- GEMM NT split-K: C[M,N] += A[:,kz] * B[:,kz]^T  (atomic epilogue) ----
template <int M, int N, int KA, int KLEN>
__device__ __forceinline__ void gemm_nt_atomic(const float* __restrict__ A,
                                               const float* __restrict__ B,
                                               float* __restrict__ C) {
    __shared__ float As[16][64];
    __shared__ float Bs[16][64];
    int t = threadIdx.x;
    int tx = t & 15;   // 16 col groups of 4
    int ty = t >> 4;   // 8 row groups of 8
    int bm = blockIdx.y * 64;
    int bn = blockIdx.x * 64;

    const float* Ab = A + blockIdx.z * KLEN;
    const float* Bb = B + blockIdx.z * KLEN;

    int r0 = t >> 2;            int kk0 = (t & 3) * 4;
    int r1 = (t + 128) >> 2;    int kk1 = ((t + 128) & 3) * 4;

    float acc[8][4];
    #pragma unroll
    for (int i = 0; i < 8; i++)
        #pragma unroll
        for (int j = 0; j < 4; j++) acc[i][j] = 0.f;

    // prefetch k-tile 0
    float4 va0 = *reinterpret_cast<const float4*>(&Ab[(size_t)(bm + r0) * KA + kk0]);
    float4 va1 = *reinterpret_cast<const float4*>(&Ab[(size_t)(bm + r1) * KA + kk1]);
    float4 vb0 = *reinterpret_cast<const float4*>(&Bb[(size_t)(bn + r0) * KA + kk0]);
    float4 vb1 = *reinterpret_cast<const float4*>(&Bb[(size_t)(bn + r1) * KA + kk1]);

    for (int k0 = 0; k0 < KLEN; k0 += 16) {
        As[kk0 + 0][r0] = va0.x; As[kk0 + 1][r0] = va0.y; As[kk0 + 2][r0] = va0.z; As[kk0 + 3][r0] = va0.w;
        As[kk1 + 0][r1] = va1.x; As[kk1 + 1][r1] = va1.y; As[kk1 + 2][r1] = va1.z; As[kk1 + 3][r1] = va1.w;
        Bs[kk0 + 0][r0] = vb0.x; Bs[kk0 + 1][r0] = vb0.y; Bs[kk0 + 2][r0] = vb0.z; Bs[kk0 + 3][r0] = vb0.w;
        Bs[kk1 + 0][r1] = vb1.x; Bs[kk1 + 1][r1] = vb1.y; Bs[kk1 + 2][r1] = vb1.z; Bs[kk1 + 3][r1] = vb1.w;
        __syncthreads();

        if (k0 + 16 < KLEN) {
            va0 = *reinterpret_cast<const float4*>(&Ab[(size_t)(bm + r0) * KA + k0 + 16 + kk0]);
            va1 = *reinterpret_cast<const float4*>(&Ab[(size_t)(bm + r1) * KA + k0 + 16 + kk1]);
            vb0 = *reinterpret_cast<const float4*>(&Bb[(size_t)(bn + r0) * KA + k0 + 16 + kk0]);
            vb1 = *reinterpret_cast<const float4*>(&Bb[(size_t)(bn + r1) * KA + k0 + 16 + kk1]);
        }

        #pragma unroll
        for (int kk = 0; kk < 16; kk++) {
            float a[8], bb[4];
            #pragma unroll
            for (int i = 0; i < 8; i++) a[i] = As[kk][ty * 8 + i];
            #pragma unroll
            for (int j = 0; j < 4; j++) bb[j] = Bs[kk][tx * 4 + j];
            #pragma unroll
            for (int i = 0; i < 8; i++)
                #pragma unroll
                for (int j = 0; j < 4; j++) acc[i][j] += a[i] * bb[j];
        }
        __syncthreads();
    }
    #pragma unroll
    for (int i = 0; i < 8; i++) {
        float* crow = &C[(size_t)(bm + ty * 8 + i) * N + bn + tx * 4];
        #pragma unroll
        for (int j = 0; j < 4; j++) atomicAdd(&crow[j], acc[i][j]);
    }
}

__global__ void k3_gemm_cc(const float* __restrict__ conv_w) {
    gemm_nt_atomic<BI * 3, DD, DD, 256>(g_cmat, conv_w, g_cc);
}
__global__ void k5_gemm_dot() {
    gemm_nt_atomic<BI * 3, BC, DD, 128>(g_cc, g_capv, g_dot);
}

// ---------------- K4: per-image Gram + bias dots ----------------
__global__ void k4_gram(const float* __restrict__ conv_b) {
    int i = blockIdx.x;
    int tid = threadIdx.x; // 128
    const float* c0 = g_cc + (size_t)(i * 3 + 0) * DD;
    const float* c1 = c0 + DD;
    const float* c2 = c1 + DD;
    float a[9];
    #pragma unroll
    for (int r = 0; r < 9; r++) a[r] = 0.f;
    for (int d = tid; d < DD; d += 128) {
        float x0 = c0[d], x1 = c1[d], x2 = c2[d], cb = conv_b[d];
        a[0] += x0 * x0; a[1] += x0 * x1; a[2] += x0 * x2;
        a[3] += x1 * x1; a[4] += x1 * x2; a[5] += x2 * x2;
        a[6] += x0 * cb; a[7] += x1 * cb; a[8] += x2 * cb;
    }
    __shared__ float s[128];
    for (int r = 0; r < 9; r++) {
        s[tid] = a[r]; __syncthreads();
        for (int off = 64; off > 0; off >>= 1) { if (tid < off) s[tid] += s[tid + off]; __syncthreads(); }
        if (tid == 0) { if (r < 6) g_G[i * 6 + r] = s[0]; else g_h[i * 3 + (r - 6)] = s[0]; }
        __syncthreads();
    }
}

// ---------------- K6: final similarity ----------------
__global__ void k6_final(float* __restrict__ out) {
    int i = blockIdx.x;
    int b = threadIdx.x; // 256
    float w0 = g_w[b * 3 + 0], w1 = g_w[b * 3 + 1], w2 = g_w[b * 3 + 2];
    const float* dp = g_dot + (size_t)(i * 3) * BC + b;
    float num = w0 * dp[0] + w1 * dp[BC] + w2 * dp[2 * BC] + g_bb[b];
    const float* G = g_G + i * 6;
    const float* h = g_h + i * 3;
    float n2 = w0 * w0 * G[0] + 2.f * w0 * w1 * G[1] + 2.f * w0 * w2 * G[2]
             + w1 * w1 * G[3] + 2.f * w1 * w2 * G[4] + w2 * w2 * G[5]
             + 2.f * (w0 * h[0] + w1 * h[1] + w2 * h[2]) + g_cb2;
    out[i * BC + b] = num / (sqrtf(n2) + EPS);
}

// ---------------- launch ----------------
extern "C" void kernel_launch(void* const* d_in, const int* in_sizes, int n_in,
                              void* d_out, int out_size) {
    const float* img    = (const float*)d_in[0];
    const float* cap    = (const float*)d_in[1];
    const int*   lens   = (const int*)d_in[2];
    const float* red_w  = (const float*)d_in[3];
    const float* red_b  = (const float*)d_in[4];
    const float* proj_w = (const float*)d_in[5];
    const float* proj_b = (const float*)d_in[6];
    const float* conv_w = (const float*)d_in[7];
    const float* conv_b = (const float*)d_in[8];
    float* out = (float*)d_out;

    float* cc_ptr = nullptr;
    float* dot_ptr = nullptr;
    float* capsum_ptr = nullptr;
    cudaGetSymbolAddress((void**)&cc_ptr, g_cc);
    cudaGetSymbolAddress((void**)&dot_ptr, g_dot);
    cudaGetSymbolAddress((void**)&capsum_ptr, g_capsum);

    k0_prep<<<9, 128>>>(red_w, red_b, proj_w, proj_b, conv_b);
    kzero<<<(BC * DD / 4 + 255) / 256, 256>>>(capsum_ptr, BC * DD / 4);
    k1a_capsum<<<dim3(BC, 4), 256>>>(cap, lens);
    k1b_caption<<<BC, 256>>>(lens, conv_b);
    k2_image<<<BI, 256>>>(img);
    kzero<<<(BI * 3 * DD / 4 + 255) / 256, 256>>>(cc_ptr, BI * 3 * DD / 4);
    // k3: C(768x1024) += cmat * conv_w^T, split-K 4 -> 768 CTAs
    k3_gemm_cc<<<dim3(DD / 64, (BI * 3) / 64, 4), 128>>>(conv_w);
    k4_gram<<<BI, 128>>>(conv_b);
    kzero<<<(BI * 3 * BC / 4 + 255) / 256, 256>>>(dot_ptr, BI * 3 * BC / 4);
    // k5: dot(768x256) += cc * capv^T, split-K 8 -> 384 CTAs
    k5_gemm_dot<<<dim3(BC / 64, (BI * 3) / 64, 8), 128>>>();
    k6_final<<<BI, 256>>>(out);
}

// round 7
// speedup vs baseline: 1.9981x; 1.4149x over previous
#include <cuda_runtime.h>
#include <math.h>

#define BI 256
#define BC 256
#define LR 36
#define TT 64
#define DD 1024
#define DR 256
#define EPS 1e-8f

// ---------------- scratch (device globals; no allocation allowed) ----------------
// capsum / cc / dot live in one contiguous buffer so a single kzero clears all.
#define ZB_CAPSUM 0
#define ZB_CC     (BC * DD)
#define ZB_DOT    (BC * DD + BI * 3 * DD)
#define ZB_TOTAL  (BC * DD + BI * 3 * DD + BI * 3 * BC)
__device__ float g_zbuf[ZB_TOTAL];
#define g_capsum (g_zbuf + ZB_CAPSUM)
#define g_cc     (g_zbuf + ZB_CC)
#define g_dot    (g_zbuf + ZB_DOT)

__device__ float g_pr[3 * DD];        // proj_w @ red_w  (3, D)
__device__ float g_pb2[3];            // proj_w @ red_b + proj_b
__device__ float g_cb2;               // ||conv_b||^2
__device__ float g_capv[BC * DD];     // l2-normalized caption means
__device__ float g_w[BC * 3];         // softmax filter weights
__device__ float g_bb[BC];            // conv_b . cap_v
__device__ float g_cmat[BI * 3 * DD]; // c[i,k,:]
__device__ float g_G[BI * 6];         // Gram cc_k . cc_k'
__device__ float g_h[BI * 3];         // cc_k . conv_b

// ---------------- K0: tiny precompute ----------------
__global__ void k0_prep(const float* __restrict__ red_w, const float* __restrict__ red_b,
                        const float* __restrict__ proj_w, const float* __restrict__ proj_b,
                        const float* __restrict__ conv_b) {
    if (blockIdx.x < 8) {
        int d = blockIdx.x * 128 + threadIdx.x;
        float a0 = 0.f, a1 = 0.f, a2 = 0.f;
        for (int e = 0; e < DR; e++) {
            float rw = red_w[e * DD + d];
            a0 += proj_w[e] * rw;
            a1 += proj_w[DR + e] * rw;
            a2 += proj_w[2 * DR + e] * rw;
        }
        g_pr[d] = a0; g_pr[DD + d] = a1; g_pr[2 * DD + d] = a2;
    } else {
        __shared__ float s[128];
        int tid = threadIdx.x;
        for (int k = 0; k < 3; k++) {
            float p = 0.f;
            for (int e = tid; e < DR; e += 128) p += proj_w[k * DR + e] * red_b[e];
            s[tid] = p; __syncthreads();
            for (int off = 64; off > 0; off >>= 1) { if (tid < off) s[tid] += s[tid + off]; __syncthreads(); }
            if (tid == 0) g_pb2[k] = s[0] + proj_b[k];
            __syncthreads();
        }
        float c = 0.f;
        for (int d = tid; d < DD; d += 128) { float v = conv_b[d]; c += v * v; }
        s[tid] = c; __syncthreads();
        for (int off = 64; off > 0; off >>= 1) { if (tid < off) s[tid] += s[tid + off]; __syncthreads(); }
        if (tid == 0) g_cb2 = s[0];
    }
}

// ---------------- K1a: t-split caption sums (atomic accumulate) ----------------
__global__ void k1a_capsum(const float* __restrict__ cap, const int* __restrict__ lens) {
    int b = blockIdx.x;
    int z = blockIdx.y;
    int tid = threadIdx.x;
    int len = lens[b];
    int t0 = z * 16;
    if (t0 >= len) return;
    int t1 = min(len, t0 + 16);
    const float* base = cap + (size_t)b * TT * DD;
    float acc[4] = {0.f, 0.f, 0.f, 0.f};
    for (int t = t0; t < t1; t++) {
        const float* row = base + t * DD;
        #pragma unroll
        for (int j = 0; j < 4; j++) acc[j] += row[tid + 256 * j];
    }
    #pragma unroll
    for (int j = 0; j < 4; j++) atomicAdd(&g_capsum[b * DD + tid + 256 * j], acc[j]);
}

// ---------------- K1b: normalize + softmax weights ----------------
__global__ void k1b_caption(const int* __restrict__ lens, const float* __restrict__ conv_b) {
    int b = blockIdx.x;
    int tid = threadIdx.x; // 256 threads, 4 channels each
    int len = lens[b];
    float invlen = 1.0f / (float)len;
    float acc[4];
    #pragma unroll
    for (int j = 0; j < 4; j++) acc[j] = g_capsum[b * DD + tid + 256 * j] * invlen;

    __shared__ float s[256];
    __shared__ float res[6];
    float vals[5];
    vals[0] = acc[0] * acc[0] + acc[1] * acc[1] + acc[2] * acc[2] + acc[3] * acc[3];
    #pragma unroll
    for (int k = 0; k < 3; k++) {
        float v = 0.f;
        #pragma unroll
        for (int j = 0; j < 4; j++) v += g_pr[k * DD + tid + 256 * j] * acc[j];
        vals[1 + k] = v;
    }
    {
        float v = 0.f;
        #pragma unroll
        for (int j = 0; j < 4; j++) v += conv_b[tid + 256 * j] * acc[j];
        vals[4] = v;
    }
    for (int r = 0; r < 5; r++) {
        s[tid] = vals[r]; __syncthreads();
        for (int off = 128; off > 0; off >>= 1) { if (tid < off) s[tid] += s[tid + off]; __syncthreads(); }
        if (tid == 0) res[r] = s[0];
        __syncthreads();
    }
    if (tid == 0) {
        float inv = 1.0f / (sqrtf(res[0]) + EPS);
        float l0 = res[1] + g_pb2[0], l1 = res[2] + g_pb2[1], l2 = res[3] + g_pb2[2];
        float m = fmaxf(l0, fmaxf(l1, l2));
        float e0 = expf(l0 - m), e1 = expf(l1 - m), e2 = expf(l2 - m);
        float si = 1.0f / (e0 + e1 + e2);
        g_w[b * 3 + 0] = e0 * si;
        g_w[b * 3 + 1] = e1 * si;
        g_w[b * 3 + 2] = e2 * si;
        g_bb[b] = res[4] * inv;
        res[5] = inv;
    }
    __syncthreads();
    float inv = res[5];
    #pragma unroll
    for (int j = 0; j < 4; j++) g_capv[b * DD + tid + 256 * j] = acc[j] * inv;
}

// ---------------- K2: image shifted region sums ----------------
__global__ void k2_image(const float* __restrict__ img) {
    int i = blockIdx.x;
    int tid = threadIdx.x;
    const float* base = img + (size_t)i * LR * DD;
    float acc[4] = {0.f, 0.f, 0.f, 0.f}, r0[4], rL[4];
    #pragma unroll
    for (int j = 0; j < 4; j++) r0[j] = base[tid + 256 * j];
    for (int t = 0; t < LR; t++) {
        #pragma unroll
        for (int j = 0; j < 4; j++) acc[j] += base[t * DD + tid + 256 * j];
    }
    #pragma unroll
    for (int j = 0; j < 4; j++) rL[j] = base[(LR - 1) * DD + tid + 256 * j];
    const float invL = 1.0f / (float)LR;
    #pragma unroll
    for (int j = 0; j < 4; j++) {
        int d = tid + 256 * j;
        g_cmat[(size_t)(i * 3 + 0) * DD + d] = (acc[j] - rL[j]) * invL;
        g_cmat[(size_t)(i * 3 + 1) * DD + d] = acc[j] * invL;
        g_cmat[(size_t)(i * 3 + 2) * DD + d] = (acc[j] - r0[j]) * invL;
    }
}

// ---------------- zero kernel (whole zbuf in one launch) ----------------
__global__ void kzero(float* __restrict__ p, int n4) {
    int i = blockIdx.x * 256 + threadIdx.x;
    if (i < n4) reinterpret_cast<float4*>(p)[i] = make_float4(0.f, 0.f, 0.f, 0.f);
}

// ---------------- GEMM NT split-K: C[M,N] += A[:,kz] * B[:,kz]^T  (atomic epilogue) ----
template <int M, int N, int KA, int KLEN>
__device__ __forceinline__ void gemm_nt_atomic(const float* __restrict__ A,
                                               const float* __restrict__ B,
                                               float* __restrict__ C) {
    __shared__ float As[16][64];
    __shared__ float Bs[16][64];
    int t = threadIdx.x;
    int tx = t & 15;
    int ty = t >> 4;
    int bm = blockIdx.y * 64;
    int bn = blockIdx.x * 64;

    const float* Ab = A + blockIdx.z * KLEN;
    const float* Bb = B + blockIdx.z * KLEN;

    int r0 = t >> 2;            int kk0 = (t & 3) * 4;
    int r1 = (t + 128) >> 2;    int kk1 = ((t + 128) & 3) * 4;

    float acc[8][4];
    #pragma unroll
    for (int i = 0; i < 8; i++)
        #pragma unroll
        for (int j = 0; j < 4; j++) acc[i][j] = 0.f;

    float4 va0 = *reinterpret_cast<const float4*>(&Ab[(size_t)(bm + r0) * KA + kk0]);
    float4 va1 = *reinterpret_cast<const float4*>(&Ab[(size_t)(bm + r1) * KA + kk1]);
    float4 vb0 = *reinterpret_cast<const float4*>(&Bb[(size_t)(bn + r0) * KA + kk0]);
    float4 vb1 = *reinterpret_cast<const float4*>(&Bb[(size_t)(bn + r1) * KA + kk1]);

    for (int k0 = 0; k0 < KLEN; k0 += 16) {
        As[kk0 + 0][r0] = va0.x; As[kk0 + 1][r0] = va0.y; As[kk0 + 2][r0] = va0.z; As[kk0 + 3][r0] = va0.w;
        As[kk1 + 0][r1] = va1.x; As[kk1 + 1][r1] = va1.y; As[kk1 + 2][r1] = va1.z; As[kk1 + 3][r1] = va1.w;
        Bs[kk0 + 0][r0] = vb0.x; Bs[kk0 + 1][r0] = vb0.y; Bs[kk0 + 2][r0] = vb0.z; Bs[kk0 + 3][r0] = vb0.w;
        Bs[kk1 + 0][r1] = vb1.x; Bs[kk1 + 1][r1] = vb1.y; Bs[kk1 + 2][r1] = vb1.z; Bs[kk1 + 3][r1] = vb1.w;
        __syncthreads();

        if (k0 + 16 < KLEN) {
            va0 = *reinterpret_cast<const float4*>(&Ab[(size_t)(bm + r0) * KA + k0 + 16 + kk0]);
            va1 = *reinterpret_cast<const float4*>(&Ab[(size_t)(bm + r1) * KA + k0 + 16 + kk1]);
            vb0 = *reinterpret_cast<const float4*>(&Bb[(size_t)(bn + r0) * KA + k0 + 16 + kk0]);
            vb1 = *reinterpret_cast<const float4*>(&Bb[(size_t)(bn + r1) * KA + k0 + 16 + kk1]);
        }

        #pragma unroll
        for (int kk = 0; kk < 16; kk++) {
            float a[8], bb[4];
            #pragma unroll
            for (int i = 0; i < 8; i++) a[i] = As[kk][ty * 8 + i];
            #pragma unroll
            for (int j = 0; j < 4; j++) bb[j] = Bs[kk][tx * 4 + j];
            #pragma unroll
            for (int i = 0; i < 8; i++)
                #pragma unroll
                for (int j = 0; j < 4; j++) acc[i][j] += a[i] * bb[j];
        }
        __syncthreads();
    }
    #pragma unroll
    for (int i = 0; i < 8; i++) {
        float* crow = &C[(size_t)(bm + ty * 8 + i) * N + bn + tx * 4];
        #pragma unroll
        for (int j = 0; j < 4; j++) atomicAdd(&crow[j], acc[i][j]);
    }
}

__global__ void k3_gemm_cc(const float* __restrict__ conv_w) {
    gemm_nt_atomic<BI * 3, DD, DD, 256>(g_cmat, conv_w, g_cc);
}
__global__ void k5_gemm_dot() {
    gemm_nt_atomic<BI * 3, BC, DD, 128>(g_cc, g_capv, g_dot);
}

// ---------------- K4: per-image Gram + bias dots ----------------
__global__ void k4_gram(const float* __restrict__ conv_b) {
    int i = blockIdx.x;
    int tid = threadIdx.x; // 128
    const float* c0 = g_cc + (size_t)(i * 3 + 0) * DD;
    const float* c1 = c0 + DD;
    const float* c2 = c1 + DD;
    float a[9];
    #pragma unroll
    for (int r = 0; r < 9; r++) a[r] = 0.f;
    for (int d = tid; d < DD; d += 128) {
        float x0 = c0[d], x1 = c1[d], x2 = c2[d], cb = conv_b[d];
        a[0] += x0 * x0; a[1] += x0 * x1; a[2] += x0 * x2;
        a[3] += x1 * x1; a[4] += x1 * x2; a[5] += x2 * x2;
        a[6] += x0 * cb; a[7] += x1 * cb; a[8] += x2 * cb;
    }
    __shared__ float s[128];
    for (int r = 0; r < 9; r++) {
        s[tid] = a[r]; __syncthreads();
        for (int off = 64; off > 0; off >>= 1) { if (tid < off) s[tid] += s[tid + off]; __syncthreads(); }
        if (tid == 0) { if (r < 6) g_G[i * 6 + r] = s[0]; else g_h[i * 3 + (r - 6)] = s[0]; }
        __syncthreads();
    }
}

// ---------------- K6: final similarity ----------------
__global__ void k6_final(float* __restrict__ out) {
    int i = blockIdx.x;
    int b = threadIdx.x; // 256
    float w0 = g_w[b * 3 + 0], w1 = g_w[b * 3 + 1], w2 = g_w[b * 3 + 2];
    const float* dp = g_dot + (size_t)(i * 3) * BC + b;
    float num = w0 * dp[0] + w1 * dp[BC] + w2 * dp[2 * BC] + g_bb[b];
    const float* G = g_G + i * 6;
    const float* h = g_h + i * 3;
    float n2 = w0 * w0 * G[0] + 2.f * w0 * w1 * G[1] + 2.f * w0 * w2 * G[2]
             + w1 * w1 * G[3] + 2.f * w1 * w2 * G[4] + w2 * w2 * G[5]
             + 2.f * (w0 * h[0] + w1 * h[1] + w2 * h[2]) + g_cb2;
    out[i * BC + b] = num / (sqrtf(n2) + EPS);
}

// ---------------- launch (fork-join: caption chain ∥ image chain) ----------------
extern "C" void kernel_launch(void* const* d_in, const int* in_sizes, int n_in,
                              void* d_out, int out_size) {
    const float* img    = (const float*)d_in[0];
    const float* cap    = (const float*)d_in[1];
    const int*   lens   = (const int*)d_in[2];
    const float* red_w  = (const float*)d_in[3];
    const float* red_b  = (const float*)d_in[4];
    const float* proj_w = (const float*)d_in[5];
    const float* proj_b = (const float*)d_in[6];
    const float* conv_w = (const float*)d_in[7];
    const float* conv_b = (const float*)d_in[8];
    float* out = (float*)d_out;

    float* zbuf = nullptr;
    cudaGetSymbolAddress((void**)&zbuf, g_zbuf);

    // Fork-join streams/events. Created per call; NOT destroyed here — destroying
    // a forked stream while the origin stream is still capturing invalidates the
    // capture. Host-side handles only (no device memory); kernel_launch is called
    // O(1) times by the harness, so the leak is bounded and harmless.
    cudaStream_t s2;
    cudaStreamCreateWithFlags(&s2, cudaStreamNonBlocking);
    cudaEvent_t e_zero, e_cap;
    cudaEventCreateWithFlags(&e_zero, cudaEventDisableTiming);
    cudaEventCreateWithFlags(&e_cap, cudaEventDisableTiming);

    // main stream: zero everything, then image chain
    kzero<<<(ZB_TOTAL / 4 + 255) / 256, 256>>>(zbuf, ZB_TOTAL / 4);
    cudaEventRecord(e_zero, 0);

    // forked stream: caption chain (joins capture via the event wait)
    cudaStreamWaitEvent(s2, e_zero, 0);
    k0_prep<<<9, 128, 0, s2>>>(red_w, red_b, proj_w, proj_b, conv_b);
    k1a_capsum<<<dim3(BC, 4), 256, 0, s2>>>(cap, lens);
    k1b_caption<<<BC, 256, 0, s2>>>(lens, conv_b);
    cudaEventRecord(e_cap, s2);

    // main stream: image chain (overlaps with caption chain)
    k2_image<<<BI, 256>>>(img);
    k3_gemm_cc<<<dim3(DD / 64, (BI * 3) / 64, 4), 128>>>(conv_w);
    k4_gram<<<BI, 128>>>(conv_b);

    // join, then final GEMM + similarity
    cudaStreamWaitEvent(0, e_cap, 0);
    k5_gemm_dot<<<dim3(BC / 64, (BI * 3) / 64, 8), 128>>>();
    k6_final<<<BI, 256>>>(out);
}